// round 2
// baseline (speedup 1.0000x reference)
#include <cuda_runtime.h>
#include <cuda_fp16.h>
#include <cstdint>
#include <cstddef>

// ============================================================================
// Problem sizes (fixed): B=16, S=512, D_IN=4096, D_OUT=1024
// ============================================================================
constexpr int M = 8192;   // B*S rows
constexpr int K = 4096;   // D_IN
constexpr int N = 1024;   // D_OUT

constexpr int BM = 128;
constexpr int BN = 128;
constexpr int BK = 64;               // fp16 elems per K stage (128 B per row)
constexpr int STAGES = 3;
constexpr int NK = K / BK;           // 64 stages along K

constexpr int STAGE_BYTES_A = BM * BK * 2;               // 16384
constexpr int STAGE_BYTES   = 2 * STAGE_BYTES_A;         // A + B = 32768
constexpr int SMEM_GEMM     = STAGES * STAGE_BYTES;      // 98304

// ============================================================================
// Device scratch (static globals — no allocation allowed)
// ============================================================================
__device__ __half g_Ah[(size_t)M * K];   // 64 MB  (hidden_states in fp16)
__device__ __half g_Bs[(size_t)N * K];   // 8 MB   (sign(W) in fp16, K-major)
__device__ float  g_alpha[N];
__device__ float  g_C[(size_t)M * N];    // 32 MB  (raw sign-GEMM result)

// ============================================================================
// Helpers
// ============================================================================
__device__ __forceinline__ uint32_t smem_to_u32(const void* p) {
    uint32_t a;
    asm("{ .reg .u64 t; cvta.to.shared.u64 t, %1; cvt.u32.u64 %0, t; }" : "=r"(a) : "l"(p));
    return a;
}
__device__ __forceinline__ uint32_t sw128(uint32_t off) {   // XOR swizzle (16B granules in 128B rows)
    return off ^ ((off >> 3) & 0x70);
}
__device__ __forceinline__ void cp16(uint32_t dst, const void* src) {
    asm volatile("cp.async.cg.shared.global [%0], [%1], 16;" :: "r"(dst), "l"(src));
}
__device__ __forceinline__ void ldsm_x4(uint32_t* r, uint32_t addr) {
    asm volatile("ldmatrix.sync.aligned.m8n8.x4.shared.b16 {%0,%1,%2,%3}, [%4];"
                 : "=r"(r[0]), "=r"(r[1]), "=r"(r[2]), "=r"(r[3]) : "r"(addr));
}
__device__ __forceinline__ void mma16816(float* c, const uint32_t* a, uint32_t b0, uint32_t b1) {
    asm volatile(
        "mma.sync.aligned.m16n8k16.row.col.f32.f16.f16.f32 "
        "{%0,%1,%2,%3}, {%4,%5,%6,%7}, {%8,%9}, {%0,%1,%2,%3};"
        : "+f"(c[0]), "+f"(c[1]), "+f"(c[2]), "+f"(c[3])
        : "r"(a[0]), "r"(a[1]), "r"(a[2]), "r"(a[3]), "r"(b0), "r"(b1));
}

// ============================================================================
// Kernel 1: W prep — alpha[o] = mean|W[o,:]| ; g_Bs = sign(W) in fp16 (K-major)
// ============================================================================
__global__ void __launch_bounds__(256) prep_w_kernel(const float* __restrict__ W) {
    const size_t o = blockIdx.x;
    const int t = threadIdx.x;
    const float4* w4 = reinterpret_cast<const float4*>(W + o * K);
    const __half one = __float2half(1.0f), mone = __float2half(-1.0f);
    float s = 0.f;
#pragma unroll
    for (int j = 0; j < 4; ++j) {
        float4 v = w4[j * 256 + t];
        s += fabsf(v.x) + fabsf(v.y) + fabsf(v.z) + fabsf(v.w);
        __half2 p0, p1;
        p0.x = (v.x >= 0.f) ? one : mone;
        p0.y = (v.y >= 0.f) ? one : mone;
        p1.x = (v.z >= 0.f) ? one : mone;
        p1.y = (v.w >= 0.f) ? one : mone;
        size_t base = o * K + (size_t)(j * 256 + t) * 4;
        *reinterpret_cast<__half2*>(g_Bs + base)     = p0;
        *reinterpret_cast<__half2*>(g_Bs + base + 2) = p1;
    }
#pragma unroll
    for (int ofs = 16; ofs; ofs >>= 1) s += __shfl_xor_sync(0xffffffffu, s, ofs);
    __shared__ float sh[8];
    if ((t & 31) == 0) sh[t >> 5] = s;
    __syncthreads();
    if (t == 0) {
        float tot = 0.f;
#pragma unroll
        for (int w = 0; w < 8; ++w) tot += sh[w];
        g_alpha[o] = tot * (1.0f / (float)K);
    }
}

// ============================================================================
// Kernel 2: A prep — fp32 -> fp16
// ============================================================================
__global__ void __launch_bounds__(256) prep_a_kernel(const float* __restrict__ A) {
    size_t i = ((size_t)blockIdx.x * 256 + threadIdx.x) * 4;
    float4 v = *reinterpret_cast<const float4*>(A + i);
    __half2 p0, p1;
    p0.x = __float2half_rn(v.x); p0.y = __float2half_rn(v.y);
    p1.x = __float2half_rn(v.z); p1.y = __float2half_rn(v.w);
    *reinterpret_cast<__half2*>(g_Ah + i)     = p0;
    *reinterpret_cast<__half2*>(g_Ah + i + 2) = p1;
}

// ============================================================================
// Kernel 3: GEMM — g_C[M,N] = g_Ah[M,K] x g_Bs[N,K]^T   (HMMA m16n8k16, fp32 acc)
//   CTA 128x128, BK=64, 3-stage cp.async pipeline, 8 warps in 4(M)x2(N) grid,
//   warp tile 32x64, 2 CTAs/SM.
// ============================================================================
__device__ __forceinline__ void load_stage(uint32_t sbase, int tid, int m0, int n0,
                                           int c, int buf) {
    const uint32_t st = sbase + (uint32_t)buf * STAGE_BYTES;
    const size_t k0 = (size_t)c * BK;
    // 2048 x 16B vectors: [0,1024)=A rows, [1024,2048)=B rows
#pragma unroll
    for (int v = tid; v < 2048; v += 256) {
        const int r = (v & 1023) >> 3;
        const int s = v & 7;
        const __half* src;
        uint32_t dst;
        if (v < 1024) {
            src = g_Ah + (size_t)(m0 + r) * K + k0 + (size_t)s * 8;
            dst = st + sw128((uint32_t)(r * 128 + s * 16));
        } else {
            src = g_Bs + (size_t)(n0 + r) * K + k0 + (size_t)s * 8;
            dst = st + STAGE_BYTES_A + sw128((uint32_t)(r * 128 + s * 16));
        }
        cp16(dst, src);
    }
    asm volatile("cp.async.commit_group;" ::: "memory");
}

__global__ void __launch_bounds__(256, 2) gemm_kernel() {
    extern __shared__ char smem[];
    const uint32_t sbase = smem_to_u32(smem);
    const int tid  = threadIdx.x;
    const int wid  = tid >> 5;
    const int lane = tid & 31;
    const int wr = wid >> 1;          // warp row 0..3 -> M offset 32*wr
    const int wc = wid & 1;           // warp col 0..1 -> N offset 64*wc
    const int m0 = blockIdx.x * BM;
    const int n0 = blockIdx.y * BN;

    float acc[2][8][4];
#pragma unroll
    for (int i = 0; i < 2; ++i)
#pragma unroll
        for (int j = 0; j < 8; ++j)
#pragma unroll
            for (int q = 0; q < 4; ++q) acc[i][j][q] = 0.f;

    // ldmatrix per-lane logical coords (constant across stages)
    const int a_row = wr * 32 + (lane & 15);         // + mt*16
    const int a_col16 = (lane >> 4) * 8;             // halves, + kk*16
    const int b_row = wc * 64 + (lane & 7) + ((lane >> 4) << 3);  // + nt2*16
    const int b_col16 = ((lane >> 3) & 1) * 8;       // halves, + kk*16

    // prologue: stages 0,1
    load_stage(sbase, tid, m0, n0, 0, 0);
    load_stage(sbase, tid, m0, n0, 1, 1);

    for (int c = 0; c < NK; ++c) {
        asm volatile("cp.async.wait_group 1;" ::: "memory");  // stage c resident
        __syncthreads();
        if (c + 2 < NK) load_stage(sbase, tid, m0, n0, c + 2, (c + 2) % STAGES);

        const uint32_t sA = sbase + (uint32_t)(c % STAGES) * STAGE_BYTES;
        const uint32_t sB = sA + STAGE_BYTES_A;
#pragma unroll
        for (int kk = 0; kk < 4; ++kk) {
            uint32_t afrag[2][4];
#pragma unroll
            for (int mt = 0; mt < 2; ++mt) {
                uint32_t off = (uint32_t)((a_row + mt * 16) * 128 + (kk * 16 + a_col16) * 2);
                ldsm_x4(afrag[mt], sA + sw128(off));
            }
            uint32_t bfrag[4][4];
#pragma unroll
            for (int nt2 = 0; nt2 < 4; ++nt2) {
                uint32_t off = (uint32_t)((b_row + nt2 * 16) * 128 + (kk * 16 + b_col16) * 2);
                ldsm_x4(bfrag[nt2], sB + sw128(off));
            }
#pragma unroll
            for (int mt = 0; mt < 2; ++mt)
#pragma unroll
                for (int nt2 = 0; nt2 < 4; ++nt2) {
                    mma16816(acc[mt][nt2 * 2 + 0], afrag[mt], bfrag[nt2][0], bfrag[nt2][1]);
                    mma16816(acc[mt][nt2 * 2 + 1], afrag[mt], bfrag[nt2][2], bfrag[nt2][3]);
                }
        }
        __syncthreads();   // all warps done reading buf c%3 before it is refilled
    }

    // Epilogue: accumulators -> g_C
    const int er = lane >> 2;           // 0..7
    const int ec = (lane & 3) * 2;      // 0,2,4,6
#pragma unroll
    for (int mt = 0; mt < 2; ++mt) {
#pragma unroll
        for (int nt = 0; nt < 8; ++nt) {
            const size_t row = (size_t)m0 + wr * 32 + mt * 16 + er;
            const int col = n0 + wc * 64 + nt * 8 + ec;
            float2 v0 = make_float2(acc[mt][nt][0], acc[mt][nt][1]);
            float2 v1 = make_float2(acc[mt][nt][2], acc[mt][nt][3]);
            *reinterpret_cast<float2*>(g_C + row * N + col)       = v0;
            *reinterpret_cast<float2*>(g_C + (row + 8) * N + col) = v1;
        }
    }
}

// ============================================================================
// Kernel 4: epilogue — x = C*alpha + b + residual ; LayerNorm(x)
// one block per row (1024 cols, 256 threads x float4)
// ============================================================================
__global__ void __launch_bounds__(256) ln_kernel(const float* __restrict__ resid,
                                                 const float* __restrict__ bias,
                                                 const float* __restrict__ gamma,
                                                 const float* __restrict__ beta,
                                                 float* __restrict__ out) {
    const size_t row = blockIdx.x;
    const int t = threadIdx.x;
    const float4 cv = reinterpret_cast<const float4*>(g_C + row * N)[t];
    const float4 iv = reinterpret_cast<const float4*>(resid + row * N)[t];
    const float4 av = reinterpret_cast<const float4*>(g_alpha)[t];
    const float4 bv = reinterpret_cast<const float4*>(bias)[t];

    float x0 = fmaf(cv.x, av.x, bv.x) + iv.x;
    float x1 = fmaf(cv.y, av.y, bv.y) + iv.y;
    float x2 = fmaf(cv.z, av.z, bv.z) + iv.z;
    float x3 = fmaf(cv.w, av.w, bv.w) + iv.w;

    float s1 = x0 + x1 + x2 + x3;
    float s2 = x0 * x0 + x1 * x1 + x2 * x2 + x3 * x3;
#pragma unroll
    for (int o = 16; o; o >>= 1) {
        s1 += __shfl_xor_sync(0xffffffffu, s1, o);
        s2 += __shfl_xor_sync(0xffffffffu, s2, o);
    }
    __shared__ float sh[16];
    if ((t & 31) == 0) { sh[t >> 5] = s1; sh[8 + (t >> 5)] = s2; }
    __syncthreads();
    float S1 = 0.f, S2 = 0.f;
#pragma unroll
    for (int w = 0; w < 8; ++w) { S1 += sh[w]; S2 += sh[8 + w]; }

    const float mu  = S1 * (1.0f / (float)N);
    const float var = S2 * (1.0f / (float)N) - mu * mu;
    const float rs  = rsqrtf(var + 1e-12f);

    const float4 gv = reinterpret_cast<const float4*>(gamma)[t];
    const float4 be = reinterpret_cast<const float4*>(beta)[t];
    float4 o4;
    o4.x = fmaf((x0 - mu) * rs, gv.x, be.x);
    o4.y = fmaf((x1 - mu) * rs, gv.y, be.y);
    o4.z = fmaf((x2 - mu) * rs, gv.z, be.z);
    o4.w = fmaf((x3 - mu) * rs, gv.w, be.w);
    reinterpret_cast<float4*>(out + row * N)[t] = o4;
}

// ============================================================================
// kernel_launch (graph-capturable: kernel launches only, default stream)
// ============================================================================
extern "C" void kernel_launch(void* const* d_in, const int* in_sizes, int n_in,
                              void* d_out, int out_size) {
    (void)in_sizes; (void)n_in; (void)out_size;
    const float* hidden = (const float*)d_in[0];   // [16,512,4096]
    const float* resid  = (const float*)d_in[1];   // [16,512,1024]
    const float* W      = (const float*)d_in[2];   // [1024,4096]
    const float* bias   = (const float*)d_in[3];   // [1024]
    const float* gamma  = (const float*)d_in[4];   // [1024]
    const float* beta   = (const float*)d_in[5];   // [1024]
    float* out = (float*)d_out;                    // [16,512,1024] fp32

    prep_w_kernel<<<N, 256>>>(W);
    prep_a_kernel<<<(unsigned)(((size_t)M * K) / 1024), 256>>>(hidden);

    cudaFuncSetAttribute(gemm_kernel, cudaFuncAttributeMaxDynamicSharedMemorySize, SMEM_GEMM);
    gemm_kernel<<<dim3(M / BM, N / BN), 256, SMEM_GEMM>>>();

    ln_kernel<<<M, 256>>>(resid, bias, gamma, beta, out);
}

// round 3
// speedup vs baseline: 1.0214x; 1.0214x over previous
#include <cuda_runtime.h>
#include <cuda_fp16.h>
#include <cstdint>
#include <cstddef>

// ============================================================================
// Problem sizes (fixed): B=16, S=512, D_IN=4096, D_OUT=1024
// ============================================================================
constexpr int M = 8192;   // B*S rows
constexpr int K = 4096;   // D_IN
constexpr int N = 1024;   // D_OUT

constexpr int BM = 128;
constexpr int BN = 128;
constexpr int BK = 64;               // fp16 elems per K stage (128 B per row)
constexpr int STAGES = 3;
constexpr int NK = K / BK;           // 64 chunks along K

constexpr int STAGE_BYTES_A = BM * BK * 2;               // 16384
constexpr int STAGE_BYTES   = 2 * STAGE_BYTES_A;         // A + B = 32768
constexpr int SMEM_GEMM     = STAGES * STAGE_BYTES;      // 98304

// ============================================================================
// Device scratch (static globals — no allocation allowed)
// ============================================================================
__device__ __half g_Ah[(size_t)M * K];   // 64 MB  (hidden_states in fp16)
__device__ __half g_Bs[(size_t)N * K];   // 8 MB   (sign(W) in fp16, K-major)
__device__ float  g_alpha[N];
__device__ float  g_X[(size_t)M * N];    // 32 MB  (x = C*alpha + bias + resid)

// ============================================================================
// Helpers
// ============================================================================
__device__ __forceinline__ uint32_t smem_to_u32(const void* p) {
    uint32_t a;
    asm("{ .reg .u64 t; cvta.to.shared.u64 t, %1; cvt.u32.u64 %0, t; }" : "=r"(a) : "l"(p));
    return a;
}
__device__ __forceinline__ uint32_t sw128(uint32_t off) {   // XOR swizzle (16B granules, 128B rows)
    return off ^ ((off >> 3) & 0x70);
}
__device__ __forceinline__ void cp16(uint32_t dst, const void* src) {
    asm volatile("cp.async.cg.shared.global [%0], [%1], 16;" :: "r"(dst), "l"(src));
}
__device__ __forceinline__ void ldsm_x4(uint32_t* r, uint32_t addr) {
    asm volatile("ldmatrix.sync.aligned.m8n8.x4.shared.b16 {%0,%1,%2,%3}, [%4];"
                 : "=r"(r[0]), "=r"(r[1]), "=r"(r[2]), "=r"(r[3]) : "r"(addr));
}
__device__ __forceinline__ void mma16816(float* c, const uint32_t* a, uint32_t b0, uint32_t b1) {
    asm volatile(
        "mma.sync.aligned.m16n8k16.row.col.f32.f16.f16.f32 "
        "{%0,%1,%2,%3}, {%4,%5,%6,%7}, {%8,%9}, {%0,%1,%2,%3};"
        : "+f"(c[0]), "+f"(c[1]), "+f"(c[2]), "+f"(c[3])
        : "r"(a[0]), "r"(a[1]), "r"(a[2]), "r"(a[3]), "r"(b0), "r"(b1));
}

// ============================================================================
// Kernel 1: W prep — alpha[o] = mean|W[o,:]| ; g_Bs = sign(W) in fp16 (K-major)
// ============================================================================
__global__ void __launch_bounds__(256) prep_w_kernel(const float* __restrict__ W) {
    const size_t o = blockIdx.x;
    const int t = threadIdx.x;
    const float4* w4 = reinterpret_cast<const float4*>(W + o * K);
    const __half one = __float2half(1.0f), mone = __float2half(-1.0f);
    float s = 0.f;
#pragma unroll
    for (int j = 0; j < 4; ++j) {
        float4 v = w4[j * 256 + t];
        s += fabsf(v.x) + fabsf(v.y) + fabsf(v.z) + fabsf(v.w);
        __half2 p0, p1;
        p0.x = (v.x >= 0.f) ? one : mone;
        p0.y = (v.y >= 0.f) ? one : mone;
        p1.x = (v.z >= 0.f) ? one : mone;
        p1.y = (v.w >= 0.f) ? one : mone;
        size_t base = o * K + (size_t)(j * 256 + t) * 4;
        *reinterpret_cast<__half2*>(g_Bs + base)     = p0;
        *reinterpret_cast<__half2*>(g_Bs + base + 2) = p1;
    }
#pragma unroll
    for (int ofs = 16; ofs; ofs >>= 1) s += __shfl_xor_sync(0xffffffffu, s, ofs);
    __shared__ float sh[8];
    if ((t & 31) == 0) sh[t >> 5] = s;
    __syncthreads();
    if (t == 0) {
        float tot = 0.f;
#pragma unroll
        for (int w = 0; w < 8; ++w) tot += sh[w];
        g_alpha[o] = tot * (1.0f / (float)K);
    }
}

// ============================================================================
// Kernel 2: A prep — fp32 -> fp16
// ============================================================================
__global__ void __launch_bounds__(256) prep_a_kernel(const float* __restrict__ A) {
    size_t i = ((size_t)blockIdx.x * 256 + threadIdx.x) * 4;
    float4 v = *reinterpret_cast<const float4*>(A + i);
    __half2 p0, p1;
    p0.x = __float2half_rn(v.x); p0.y = __float2half_rn(v.y);
    p1.x = __float2half_rn(v.z); p1.y = __float2half_rn(v.w);
    *reinterpret_cast<__half2*>(g_Ah + i)     = p0;
    *reinterpret_cast<__half2*>(g_Ah + i + 2) = p1;
}

// ============================================================================
// Kernel 3: GEMM + fused epilogue
//   g_X = (g_Ah x g_Bs^T) * alpha + bias + resid
//   CTA 128x128, BK=64, 3-stage cp.async pipeline, 8 warps (32x64 warp tiles),
//   2 CTAs/SM. Loader uses precomputed pointers/offsets (issue-lean).
// ============================================================================
__global__ void __launch_bounds__(256, 2) gemm_kernel(const float* __restrict__ resid,
                                                      const float* __restrict__ bias) {
    extern __shared__ char smem[];
    const uint32_t sbase = smem_to_u32(smem);
    const int tid  = threadIdx.x;
    const int wid  = tid >> 5;
    const int lane = tid & 31;
    const int wr = wid >> 1;          // warp row 0..3 -> M offset 32*wr
    const int wc = wid & 1;           // warp col 0..1 -> N offset 64*wc
    const int n0 = blockIdx.x * BN;   // x = n (8 tiles): B L2-resident, A read once/wave
    const int m0 = blockIdx.y * BM;

    // ---- loader precompute: 4 A srcs + const A->B delta, 4 swizzled dst offs ----
    const __half* a_src[4];
    uint32_t dsto[4];
#pragma unroll
    for (int k = 0; k < 4; ++k) {
        const int vv = tid + k * 256;       // 0..1023
        const int r = vv >> 3, s = vv & 7;  // row 0..127, 16B-seg 0..7
        a_src[k] = g_Ah + (size_t)(m0 + r) * K + (size_t)s * 8;
        dsto[k] = sw128((uint32_t)(r * 128 + s * 16));
    }
    const ptrdiff_t ab_delta = (g_Bs + (size_t)n0 * K) - (g_Ah + (size_t)m0 * K);

    float acc[2][8][4];
#pragma unroll
    for (int i = 0; i < 2; ++i)
#pragma unroll
        for (int j = 0; j < 8; ++j)
#pragma unroll
            for (int q = 0; q < 4; ++q) acc[i][j][q] = 0.f;

    // ldmatrix per-lane logical coords
    const int a_row = wr * 32 + (lane & 15);
    const int a_col16 = (lane >> 4) * 8;
    const int b_row = wc * 64 + (lane & 7) + ((lane >> 4) << 3);
    const int b_col16 = ((lane >> 3) & 1) * 8;

    // prologue: stages 0,1
#pragma unroll
    for (int p = 0; p < 2; ++p) {
        const uint32_t st = sbase + (uint32_t)p * STAGE_BYTES;
#pragma unroll
        for (int k = 0; k < 4; ++k) {
            cp16(st + dsto[k], a_src[k]);
            cp16(st + STAGE_BYTES_A + dsto[k], a_src[k] + ab_delta);
            a_src[k] += BK;
        }
        asm volatile("cp.async.commit_group;" ::: "memory");
    }

    for (int c = 0; c < NK; ++c) {
        asm volatile("cp.async.wait_group 1;" ::: "memory");  // stage c resident
        __syncthreads();   // also guards buf (c-1)%3 reuse below

        if (c + 2 < NK) {
            const uint32_t st = sbase + (uint32_t)((c + 2) % STAGES) * STAGE_BYTES;
#pragma unroll
            for (int k = 0; k < 4; ++k) {
                cp16(st + dsto[k], a_src[k]);
                cp16(st + STAGE_BYTES_A + dsto[k], a_src[k] + ab_delta);
                a_src[k] += BK;
            }
        }
        asm volatile("cp.async.commit_group;" ::: "memory");

        const uint32_t sA = sbase + (uint32_t)(c % STAGES) * STAGE_BYTES;
        const uint32_t sB = sA + STAGE_BYTES_A;
#pragma unroll
        for (int kk = 0; kk < 4; ++kk) {
            uint32_t afrag[2][4];
#pragma unroll
            for (int mt = 0; mt < 2; ++mt) {
                uint32_t off = (uint32_t)((a_row + mt * 16) * 128 + (kk * 16 + a_col16) * 2);
                ldsm_x4(afrag[mt], sA + sw128(off));
            }
            uint32_t bfrag[4][4];
#pragma unroll
            for (int nt2 = 0; nt2 < 4; ++nt2) {
                uint32_t off = (uint32_t)((b_row + nt2 * 16) * 128 + (kk * 16 + b_col16) * 2);
                ldsm_x4(bfrag[nt2], sB + sw128(off));
            }
#pragma unroll
            for (int mt = 0; mt < 2; ++mt)
#pragma unroll
                for (int nt2 = 0; nt2 < 4; ++nt2) {
                    mma16816(acc[mt][nt2 * 2 + 0], afrag[mt], bfrag[nt2][0], bfrag[nt2][1]);
                    mma16816(acc[mt][nt2 * 2 + 1], afrag[mt], bfrag[nt2][2], bfrag[nt2][3]);
                }
        }
    }

    // Fused epilogue: x = acc*alpha[col] + bias[col] + resid ; write g_X
    const int er = lane >> 2;           // 0..7
    const int ec = (lane & 3) * 2;      // 0,2,4,6
    const int col0 = n0 + wc * 64;
#pragma unroll
    for (int nt = 0; nt < 8; ++nt) {
        const int col = col0 + nt * 8 + ec;
        const float2 al = *reinterpret_cast<const float2*>(g_alpha + col);
        const float2 bi = *reinterpret_cast<const float2*>(bias + col);
#pragma unroll
        for (int mt = 0; mt < 2; ++mt) {
            const size_t row = (size_t)m0 + wr * 32 + mt * 16 + er;
            const float2 r0 = *reinterpret_cast<const float2*>(resid + row * N + col);
            const float2 r1 = *reinterpret_cast<const float2*>(resid + (row + 8) * N + col);
            float2 v0, v1;
            v0.x = fmaf(acc[mt][nt][0], al.x, bi.x) + r0.x;
            v0.y = fmaf(acc[mt][nt][1], al.y, bi.y) + r0.y;
            v1.x = fmaf(acc[mt][nt][2], al.x, bi.x) + r1.x;
            v1.y = fmaf(acc[mt][nt][3], al.y, bi.y) + r1.y;
            *reinterpret_cast<float2*>(g_X + row * N + col)       = v0;
            *reinterpret_cast<float2*>(g_X + (row + 8) * N + col) = v1;
        }
    }
}

// ============================================================================
// Kernel 4: LayerNorm — warp per row, shuffle-only reduction
// ============================================================================
__global__ void __launch_bounds__(256) ln_kernel(const float* __restrict__ gamma,
                                                 const float* __restrict__ beta,
                                                 float* __restrict__ out) {
    const size_t row = ((size_t)blockIdx.x * 256 + threadIdx.x) >> 5;
    const int lane = threadIdx.x & 31;
    const float4* xp = reinterpret_cast<const float4*>(g_X + row * N);

    float4 v[8];
    float s1 = 0.f, s2 = 0.f;
#pragma unroll
    for (int j = 0; j < 8; ++j) {
        v[j] = xp[lane + j * 32];
        s1 += v[j].x + v[j].y + v[j].z + v[j].w;
        s2 += v[j].x * v[j].x + v[j].y * v[j].y + v[j].z * v[j].z + v[j].w * v[j].w;
    }
#pragma unroll
    for (int o = 16; o; o >>= 1) {
        s1 += __shfl_xor_sync(0xffffffffu, s1, o);
        s2 += __shfl_xor_sync(0xffffffffu, s2, o);
    }
    const float mu  = s1 * (1.0f / (float)N);
    const float var = s2 * (1.0f / (float)N) - mu * mu;
    const float rs  = rsqrtf(var + 1e-12f);

    float4* op = reinterpret_cast<float4*>(out + row * N);
    const float4* gp = reinterpret_cast<const float4*>(gamma);
    const float4* bp = reinterpret_cast<const float4*>(beta);
#pragma unroll
    for (int j = 0; j < 8; ++j) {
        const float4 g = gp[lane + j * 32];
        const float4 b = bp[lane + j * 32];
        float4 o4;
        o4.x = fmaf((v[j].x - mu) * rs, g.x, b.x);
        o4.y = fmaf((v[j].y - mu) * rs, g.y, b.y);
        o4.z = fmaf((v[j].z - mu) * rs, g.z, b.z);
        o4.w = fmaf((v[j].w - mu) * rs, g.w, b.w);
        op[lane + j * 32] = o4;
    }
}

// ============================================================================
// kernel_launch (graph-capturable: kernel launches only, default stream)
// ============================================================================
extern "C" void kernel_launch(void* const* d_in, const int* in_sizes, int n_in,
                              void* d_out, int out_size) {
    (void)in_sizes; (void)n_in; (void)out_size;
    const float* hidden = (const float*)d_in[0];   // [16,512,4096]
    const float* resid  = (const float*)d_in[1];   // [16,512,1024]
    const float* W      = (const float*)d_in[2];   // [1024,4096]
    const float* bias   = (const float*)d_in[3];   // [1024]
    const float* gamma  = (const float*)d_in[4];   // [1024]
    const float* beta   = (const float*)d_in[5];   // [1024]
    float* out = (float*)d_out;                    // [16,512,1024] fp32

    prep_w_kernel<<<N, 256>>>(W);
    prep_a_kernel<<<(unsigned)(((size_t)M * K) / 1024), 256>>>(hidden);

    cudaFuncSetAttribute(gemm_kernel, cudaFuncAttributeMaxDynamicSharedMemorySize, SMEM_GEMM);
    gemm_kernel<<<dim3(N / BN, M / BM), 256, SMEM_GEMM>>>(resid, bias);

    ln_kernel<<<M / 8, 256>>>(gamma, beta, out);
}

// round 4
// speedup vs baseline: 1.0656x; 1.0433x over previous
#include <cuda_runtime.h>
#include <cuda_fp16.h>
#include <cstdint>
#include <cstddef>

// ============================================================================
// Problem sizes (fixed): B=16, S=512, D_IN=4096, D_OUT=1024
// ============================================================================
constexpr int M = 8192;   // B*S rows
constexpr int K = 4096;   // D_IN
constexpr int N = 1024;   // D_OUT

constexpr int BM = 128;
constexpr int BN = 128;
constexpr int BK = 64;               // fp16 elems per K stage (128 B per row)
constexpr int STAGES = 3;
constexpr int NK = K / BK;           // 64 chunks along K
constexpr int GTHREADS = 128;        // 4 warps, 64x64 warp tiles

constexpr int STAGE_BYTES_A = BM * BK * 2;               // 16384
constexpr int STAGE_BYTES   = 2 * STAGE_BYTES_A;         // A + B = 32768
constexpr int SMEM_GEMM     = STAGES * STAGE_BYTES;      // 98304

// ============================================================================
// Device scratch (static globals — no allocation allowed)
// ============================================================================
__device__ __half g_Ah[(size_t)M * K];   // 64 MB  (hidden_states in fp16)
__device__ __half g_Bs[(size_t)N * K];   // 8 MB   (sign(W) in fp16, K-major)
__device__ float  g_alpha[N];
__device__ float  g_X[(size_t)M * N];    // 32 MB  (x = C*alpha + bias + resid)

// ============================================================================
// Helpers
// ============================================================================
__device__ __forceinline__ uint32_t smem_to_u32(const void* p) {
    uint32_t a;
    asm("{ .reg .u64 t; cvta.to.shared.u64 t, %1; cvt.u32.u64 %0, t; }" : "=r"(a) : "l"(p));
    return a;
}
__device__ __forceinline__ uint32_t sw128(uint32_t off) {   // XOR swizzle (16B granules, 128B rows)
    return off ^ ((off >> 3) & 0x70);
}
__device__ __forceinline__ void cp16(uint32_t dst, const void* src) {
    asm volatile("cp.async.cg.shared.global [%0], [%1], 16;" :: "r"(dst), "l"(src));
}
__device__ __forceinline__ void ldsm_x4(uint32_t* r, uint32_t addr) {
    asm volatile("ldmatrix.sync.aligned.m8n8.x4.shared.b16 {%0,%1,%2,%3}, [%4];"
                 : "=r"(r[0]), "=r"(r[1]), "=r"(r[2]), "=r"(r[3]) : "r"(addr));
}
__device__ __forceinline__ void mma16816(float* c, const uint32_t* a, uint32_t b0, uint32_t b1) {
    asm volatile(
        "mma.sync.aligned.m16n8k16.row.col.f32.f16.f16.f32 "
        "{%0,%1,%2,%3}, {%4,%5,%6,%7}, {%8,%9}, {%0,%1,%2,%3};"
        : "+f"(c[0]), "+f"(c[1]), "+f"(c[2]), "+f"(c[3])
        : "r"(a[0]), "r"(a[1]), "r"(a[2]), "r"(a[3]), "r"(b0), "r"(b1));
}

// ============================================================================
// Kernel 1: fused prep — blocks [0,N): W -> alpha + sign fp16
//                        blocks [N,...): hidden fp32 -> fp16
// ============================================================================
__global__ void __launch_bounds__(256) prep_kernel(const float* __restrict__ W,
                                                   const float* __restrict__ A) {
    if (blockIdx.x < N) {
        const size_t o = blockIdx.x;
        const int t = threadIdx.x;
        const float4* w4 = reinterpret_cast<const float4*>(W + o * K);
        const __half one = __float2half(1.0f), mone = __float2half(-1.0f);
        float s = 0.f;
#pragma unroll
        for (int j = 0; j < 4; ++j) {
            float4 v = w4[j * 256 + t];
            s += fabsf(v.x) + fabsf(v.y) + fabsf(v.z) + fabsf(v.w);
            __half2 p0, p1;
            p0.x = (v.x >= 0.f) ? one : mone;
            p0.y = (v.y >= 0.f) ? one : mone;
            p1.x = (v.z >= 0.f) ? one : mone;
            p1.y = (v.w >= 0.f) ? one : mone;
            size_t base = o * K + (size_t)(j * 256 + t) * 4;
            *reinterpret_cast<__half2*>(g_Bs + base)     = p0;
            *reinterpret_cast<__half2*>(g_Bs + base + 2) = p1;
        }
#pragma unroll
        for (int ofs = 16; ofs; ofs >>= 1) s += __shfl_xor_sync(0xffffffffu, s, ofs);
        __shared__ float sh[8];
        if ((t & 31) == 0) sh[t >> 5] = s;
        __syncthreads();
        if (t == 0) {
            float tot = 0.f;
#pragma unroll
            for (int w = 0; w < 8; ++w) tot += sh[w];
            g_alpha[o] = tot * (1.0f / (float)K);
        }
    } else {
        size_t i = ((size_t)(blockIdx.x - N) * 256 + threadIdx.x) * 4;
        float4 v = *reinterpret_cast<const float4*>(A + i);
        __half2 p0, p1;
        p0.x = __float2half_rn(v.x); p0.y = __float2half_rn(v.y);
        p1.x = __float2half_rn(v.z); p1.y = __float2half_rn(v.w);
        *reinterpret_cast<__half2*>(g_Ah + i)     = p0;
        *reinterpret_cast<__half2*>(g_Ah + i + 2) = p1;
    }
}

// ============================================================================
// Kernel 2: GEMM + fused epilogue
//   g_X = (g_Ah x g_Bs^T) * alpha + bias + resid
//   CTA 128x128, BK=64, 3-stage cp.async pipeline, 4 warps (64x64 warp tiles),
//   2 CTAs/SM. Balanced smem-crossbar vs tensor pipe.
// ============================================================================
__global__ void __launch_bounds__(GTHREADS, 2) gemm_kernel(const float* __restrict__ resid,
                                                           const float* __restrict__ bias) {
    extern __shared__ char smem[];
    const uint32_t sbase = smem_to_u32(smem);
    const int tid  = threadIdx.x;
    const int wid  = tid >> 5;
    const int lane = tid & 31;
    const int wr = wid >> 1;          // warp row 0..1 -> M offset 64*wr
    const int wc = wid & 1;           // warp col 0..1 -> N offset 64*wc
    const int n0 = blockIdx.x * BN;   // x = n (8 tiles): B L2-resident
    const int m0 = blockIdx.y * BM;

    // ---- loader precompute: one ptr + one swizzled dst base per tensor ----
    // 128 threads x 16 vectors (8 A + 8 B). thread handles rows r0 + 16k, seg s.
    const int r0 = tid >> 3;            // 0..15
    const int s8 = tid & 7;             // 16B segment 0..7
    const __half* a_ptr = g_Ah + (size_t)(m0 + r0) * K + (size_t)s8 * 8;
    const __half* b_ptr = g_Bs + (size_t)(n0 + r0) * K + (size_t)s8 * 8;
    const uint32_t dst0 = sw128((uint32_t)(r0 * 128 + s8 * 16));
    // identity: sw128(off + k*2048) == sw128(off) + k*2048 (bits 7-9 unaffected)

    float acc[4][8][4];
#pragma unroll
    for (int i = 0; i < 4; ++i)
#pragma unroll
        for (int j = 0; j < 8; ++j)
#pragma unroll
            for (int q = 0; q < 4; ++q) acc[i][j][q] = 0.f;

    // ldmatrix per-lane logical coords
    const int a_row = wr * 64 + (lane & 15);                      // + mt*16
    const int a_col16 = (lane >> 4) * 8;                          // + kk*16
    const int b_row = wc * 64 + (lane & 7) + ((lane >> 4) << 3);  // + nt2*16
    const int b_col16 = ((lane >> 3) & 1) * 8;                    // + kk*16

    // prologue: stages 0,1
#pragma unroll
    for (int p = 0; p < 2; ++p) {
        const uint32_t st = sbase + (uint32_t)p * STAGE_BYTES;
#pragma unroll
        for (int k = 0; k < 8; ++k) {
            cp16(st + dst0 + k * 2048u, a_ptr + (size_t)p * BK + (size_t)k * 16 * K);
            cp16(st + STAGE_BYTES_A + dst0 + k * 2048u, b_ptr + (size_t)p * BK + (size_t)k * 16 * K);
        }
        asm volatile("cp.async.commit_group;" ::: "memory");
    }
    a_ptr += 2 * BK; b_ptr += 2 * BK;

    for (int c = 0; c < NK; ++c) {
        asm volatile("cp.async.wait_group 1;" ::: "memory");  // stage c resident
        __syncthreads();   // also guards buf reuse

        if (c + 2 < NK) {
            const uint32_t st = sbase + (uint32_t)((c + 2) % STAGES) * STAGE_BYTES;
#pragma unroll
            for (int k = 0; k < 8; ++k) {
                cp16(st + dst0 + k * 2048u, a_ptr + (size_t)k * 16 * K);
                cp16(st + STAGE_BYTES_A + dst0 + k * 2048u, b_ptr + (size_t)k * 16 * K);
            }
            a_ptr += BK; b_ptr += BK;
        }
        asm volatile("cp.async.commit_group;" ::: "memory");

        const uint32_t sA = sbase + (uint32_t)(c % STAGES) * STAGE_BYTES;
        const uint32_t sB = sA + STAGE_BYTES_A;
#pragma unroll
        for (int kk = 0; kk < 4; ++kk) {
            uint32_t afrag[4][4];
#pragma unroll
            for (int mt = 0; mt < 4; ++mt) {
                uint32_t off = (uint32_t)((a_row + mt * 16) * 128 + (kk * 16 + a_col16) * 2);
                ldsm_x4(afrag[mt], sA + sw128(off));
            }
            uint32_t bfrag[4][4];
#pragma unroll
            for (int nt2 = 0; nt2 < 4; ++nt2) {
                uint32_t off = (uint32_t)((b_row + nt2 * 16) * 128 + (kk * 16 + b_col16) * 2);
                ldsm_x4(bfrag[nt2], sB + sw128(off));
            }
#pragma unroll
            for (int mt = 0; mt < 4; ++mt)
#pragma unroll
                for (int nt2 = 0; nt2 < 4; ++nt2) {
                    mma16816(acc[mt][nt2 * 2 + 0], afrag[mt], bfrag[nt2][0], bfrag[nt2][1]);
                    mma16816(acc[mt][nt2 * 2 + 1], afrag[mt], bfrag[nt2][2], bfrag[nt2][3]);
                }
        }
    }

    // Fused epilogue: x = acc*alpha[col] + bias[col] + resid ; write g_X
    const int er = lane >> 2;           // 0..7
    const int ec = (lane & 3) * 2;      // 0,2,4,6
    const int col0 = n0 + wc * 64;
#pragma unroll
    for (int nt = 0; nt < 8; ++nt) {
        const int col = col0 + nt * 8 + ec;
        const float2 al = *reinterpret_cast<const float2*>(g_alpha + col);
        const float2 bi = *reinterpret_cast<const float2*>(bias + col);
#pragma unroll
        for (int mt = 0; mt < 4; ++mt) {
            const size_t row = (size_t)m0 + wr * 64 + mt * 16 + er;
            const float2 r0v = *reinterpret_cast<const float2*>(resid + row * N + col);
            const float2 r1v = *reinterpret_cast<const float2*>(resid + (row + 8) * N + col);
            float2 v0, v1;
            v0.x = fmaf(acc[mt][nt][0], al.x, bi.x) + r0v.x;
            v0.y = fmaf(acc[mt][nt][1], al.y, bi.y) + r0v.y;
            v1.x = fmaf(acc[mt][nt][2], al.x, bi.x) + r1v.x;
            v1.y = fmaf(acc[mt][nt][3], al.y, bi.y) + r1v.y;
            *reinterpret_cast<float2*>(g_X + row * N + col)       = v0;
            *reinterpret_cast<float2*>(g_X + (row + 8) * N + col) = v1;
        }
    }
}

// ============================================================================
// Kernel 3: LayerNorm — warp per row, shuffle-only reduction
// ============================================================================
__global__ void __launch_bounds__(128) ln_kernel(const float* __restrict__ gamma,
                                                 const float* __restrict__ beta,
                                                 float* __restrict__ out) {
    const size_t row = ((size_t)blockIdx.x * 128 + threadIdx.x) >> 5;
    const int lane = threadIdx.x & 31;
    const float4* xp = reinterpret_cast<const float4*>(g_X + row * N);

    float4 v[8];
    float s1 = 0.f, s2 = 0.f;
#pragma unroll
    for (int j = 0; j < 8; ++j) {
        v[j] = xp[lane + j * 32];
        s1 += v[j].x + v[j].y + v[j].z + v[j].w;
        s2 += v[j].x * v[j].x + v[j].y * v[j].y + v[j].z * v[j].z + v[j].w * v[j].w;
    }
#pragma unroll
    for (int o = 16; o; o >>= 1) {
        s1 += __shfl_xor_sync(0xffffffffu, s1, o);
        s2 += __shfl_xor_sync(0xffffffffu, s2, o);
    }
    const float mu  = s1 * (1.0f / (float)N);
    const float var = s2 * (1.0f / (float)N) - mu * mu;
    const float rs  = rsqrtf(var + 1e-12f);

    float4* op = reinterpret_cast<float4*>(out + row * N);
    const float4* gp = reinterpret_cast<const float4*>(gamma);
    const float4* bp = reinterpret_cast<const float4*>(beta);
#pragma unroll
    for (int j = 0; j < 8; ++j) {
        const float4 g = gp[lane + j * 32];
        const float4 b = bp[lane + j * 32];
        float4 o4;
        o4.x = fmaf((v[j].x - mu) * rs, g.x, b.x);
        o4.y = fmaf((v[j].y - mu) * rs, g.y, b.y);
        o4.z = fmaf((v[j].z - mu) * rs, g.z, b.z);
        o4.w = fmaf((v[j].w - mu) * rs, g.w, b.w);
        op[lane + j * 32] = o4;
    }
}

// ============================================================================
// kernel_launch (graph-capturable: kernel launches only, default stream)
// ============================================================================
extern "C" void kernel_launch(void* const* d_in, const int* in_sizes, int n_in,
                              void* d_out, int out_size) {
    (void)in_sizes; (void)n_in; (void)out_size;
    const float* hidden = (const float*)d_in[0];   // [16,512,4096]
    const float* resid  = (const float*)d_in[1];   // [16,512,1024]
    const float* W      = (const float*)d_in[2];   // [1024,4096]
    const float* bias   = (const float*)d_in[3];   // [1024]
    const float* gamma  = (const float*)d_in[4];   // [1024]
    const float* beta   = (const float*)d_in[5];   // [1024]
    float* out = (float*)d_out;                    // [16,512,1024] fp32

    // fused prep: 1024 W-blocks + 32768 A-blocks
    prep_kernel<<<N + (unsigned)(((size_t)M * K) / 1024), 256>>>(W, hidden);

    cudaFuncSetAttribute(gemm_kernel, cudaFuncAttributeMaxDynamicSharedMemorySize, SMEM_GEMM);
    gemm_kernel<<<dim3(N / BN, M / BM), GTHREADS, SMEM_GEMM>>>(resid, bias);

    ln_kernel<<<M / 4, 128>>>(gamma, beta, out);
}

// round 10
// speedup vs baseline: 1.0674x; 1.0017x over previous
#include <cuda_runtime.h>
#include <cuda_fp16.h>
#include <cstdint>
#include <cstddef>

// ============================================================================
// Problem sizes (fixed): B=16, S=512, D_IN=4096, D_OUT=1024
// ============================================================================
constexpr int M = 8192;   // B*S rows
constexpr int K = 4096;   // D_IN
constexpr int N = 1024;   // D_OUT

constexpr int BM = 128;
constexpr int BN = 128;
constexpr int BK = 64;               // fp16 elems per K stage (128 B per row)
constexpr int STAGES = 3;
constexpr int NK = K / BK;           // 64 chunks along K
constexpr int GTHREADS = 128;        // 4 warps, 64x64 warp tiles

constexpr int STAGE_BYTES_A = BM * BK * 2;               // 16384
constexpr int STAGE_BYTES   = 2 * STAGE_BYTES_A;         // A + B = 32768
constexpr int SMEM_GEMM     = STAGES * STAGE_BYTES;      // 98304

// ============================================================================
// Device scratch (static globals — no allocation allowed)
// ============================================================================
__device__ __half g_Ah[(size_t)M * K];   // 64 MB  (hidden_states in fp16)
__device__ __half g_Bs[(size_t)N * K];   // 8 MB   (sign(W) in fp16, K-major)
__device__ float  g_alpha[N];
__device__ float  g_X[(size_t)M * N];    // 32 MB  (x = C*alpha + bias + resid)

// ============================================================================
// Helpers
// ============================================================================
__device__ __forceinline__ uint32_t smem_to_u32(const void* p) {
    uint32_t a;
    asm("{ .reg .u64 t; cvta.to.shared.u64 t, %1; cvt.u32.u64 %0, t; }" : "=r"(a) : "l"(p));
    return a;
}
__device__ __forceinline__ uint32_t sw128(uint32_t off) {   // XOR swizzle (16B granules, 128B rows)
    return off ^ ((off >> 3) & 0x70);
}
__device__ __forceinline__ void cp16(uint32_t dst, const void* src) {
    asm volatile("cp.async.cg.shared.global [%0], [%1], 16;" :: "r"(dst), "l"(src));
}
__device__ __forceinline__ void ldsm_x4(uint32_t* r, uint32_t addr) {
    asm volatile("ldmatrix.sync.aligned.m8n8.x4.shared.b16 {%0,%1,%2,%3}, [%4];"
                 : "=r"(r[0]), "=r"(r[1]), "=r"(r[2]), "=r"(r[3]) : "r"(addr));
}
__device__ __forceinline__ void mma16816(float* c, const uint32_t* a, uint32_t b0, uint32_t b1) {
    asm volatile(
        "mma.sync.aligned.m16n8k16.row.col.f32.f16.f16.f32 "
        "{%0,%1,%2,%3}, {%4,%5,%6,%7}, {%8,%9}, {%0,%1,%2,%3};"
        : "+f"(c[0]), "+f"(c[1]), "+f"(c[2]), "+f"(c[3])
        : "r"(a[0]), "r"(a[1]), "r"(a[2]), "r"(a[3]), "r"(b0), "r"(b1));
}

// ============================================================================
// Kernel 1: fused prep — blocks [0,N): W -> alpha + sign fp16
//                        blocks [N,...): hidden fp32 -> fp16
//   A-branch: 4096 float4 per block = 4 groups x (4 front-batched float4/thread)
// ============================================================================
__global__ void __launch_bounds__(256) prep_kernel(const float* __restrict__ W,
                                                   const float* __restrict__ A) {
    if (blockIdx.x < N) {
        const size_t o = blockIdx.x;
        const int t = threadIdx.x;
        const float4* w4 = reinterpret_cast<const float4*>(W + o * K);
        const __half one = __float2half(1.0f), mone = __float2half(-1.0f);
        float s = 0.f;
#pragma unroll
        for (int j = 0; j < 4; ++j) {
            float4 v = w4[j * 256 + t];
            s += fabsf(v.x) + fabsf(v.y) + fabsf(v.z) + fabsf(v.w);
            __half2 p0, p1;
            p0.x = (v.x >= 0.f) ? one : mone;
            p0.y = (v.y >= 0.f) ? one : mone;
            p1.x = (v.z >= 0.f) ? one : mone;
            p1.y = (v.w >= 0.f) ? one : mone;
            size_t base = o * K + (size_t)(j * 256 + t) * 4;
            *reinterpret_cast<__half2*>(g_Bs + base)     = p0;
            *reinterpret_cast<__half2*>(g_Bs + base + 2) = p1;
        }
#pragma unroll
        for (int ofs = 16; ofs; ofs >>= 1) s += __shfl_xor_sync(0xffffffffu, s, ofs);
        __shared__ float sh[8];
        if ((t & 31) == 0) sh[t >> 5] = s;
        __syncthreads();
        if (t == 0) {
            float tot = 0.f;
#pragma unroll
            for (int w = 0; w < 8; ++w) tot += sh[w];
            g_alpha[o] = tot * (1.0f / (float)K);
        }
    } else {
        const size_t blk = (size_t)(blockIdx.x - N) * 4096;   // float4 units per block
        const float4* src = reinterpret_cast<const float4*>(A) + blk + threadIdx.x;
#pragma unroll
        for (int g = 0; g < 4; ++g) {
            float4 v[4];
#pragma unroll
            for (int j = 0; j < 4; ++j) v[j] = src[g * 1024 + j * 256];   // MLP=4 batch
#pragma unroll
            for (int j = 0; j < 4; ++j) {
                __half2 p0, p1;
                p0.x = __float2half_rn(v[j].x); p0.y = __float2half_rn(v[j].y);
                p1.x = __float2half_rn(v[j].z); p1.y = __float2half_rn(v[j].w);
                size_t e = (blk + (size_t)(g * 1024 + j * 256) + threadIdx.x) * 4;
                *reinterpret_cast<__half2*>(g_Ah + e)     = p0;
                *reinterpret_cast<__half2*>(g_Ah + e + 2) = p1;
            }
        }
    }
}

// ============================================================================
// Kernel 2: GEMM + fused epilogue
//   g_X = (g_Ah x g_Bs^T) * alpha + bias + resid
//   CTA 128x128, BK=64, 3-stage cp.async pipeline, 4 warps (64x64 warp tiles),
//   2 CTAs/SM. Fragment double-buffering over kk (hide LDSM latency).
// ============================================================================
__global__ void __launch_bounds__(GTHREADS, 2) gemm_kernel(const float* __restrict__ resid,
                                                           const float* __restrict__ bias) {
    extern __shared__ char smem[];
    const uint32_t sbase = smem_to_u32(smem);
    const int tid  = threadIdx.x;
    const int wid  = tid >> 5;
    const int lane = tid & 31;
    const int wr = wid >> 1;          // warp row 0..1 -> M offset 64*wr
    const int wc = wid & 1;           // warp col 0..1 -> N offset 64*wc
    const int n0 = blockIdx.x * BN;   // x = n (8 tiles): B L2-resident
    const int m0 = blockIdx.y * BM;

    // ---- loader precompute ----
    const int r0 = tid >> 3;            // 0..15
    const int s8 = tid & 7;             // 16B segment 0..7
    const __half* a_ptr = g_Ah + (size_t)(m0 + r0) * K + (size_t)s8 * 8;
    const __half* b_ptr = g_Bs + (size_t)(n0 + r0) * K + (size_t)s8 * 8;
    const uint32_t dst0 = sw128((uint32_t)(r0 * 128 + s8 * 16));
    // identity: sw128(off + k*2048) == sw128(off) + k*2048

    float acc[4][8][4];
#pragma unroll
    for (int i = 0; i < 4; ++i)
#pragma unroll
        for (int j = 0; j < 8; ++j)
#pragma unroll
            for (int q = 0; q < 4; ++q) acc[i][j][q] = 0.f;

    // ldmatrix per-lane coords
    const int a_row = wr * 64 + (lane & 15);
    const int a_col16 = (lane >> 4) * 8;
    const int b_row = wc * 64 + (lane & 7) + ((lane >> 4) << 3);
    const int b_col16 = ((lane >> 3) & 1) * 8;

    // prologue: stages 0,1
#pragma unroll
    for (int p = 0; p < 2; ++p) {
        const uint32_t st = sbase + (uint32_t)p * STAGE_BYTES;
#pragma unroll
        for (int k = 0; k < 8; ++k) {
            cp16(st + dst0 + k * 2048u, a_ptr + (size_t)p * BK + (size_t)k * 16 * K);
            cp16(st + STAGE_BYTES_A + dst0 + k * 2048u, b_ptr + (size_t)p * BK + (size_t)k * 16 * K);
        }
        asm volatile("cp.async.commit_group;" ::: "memory");
    }
    a_ptr += 2 * BK; b_ptr += 2 * BK;

    uint32_t af[2][4][4], bf[2][4][4];

    for (int c = 0; c < NK; ++c) {
        asm volatile("cp.async.wait_group 1;" ::: "memory");  // stage c resident
        __syncthreads();   // also guards buf reuse

        if (c + 2 < NK) {
            const uint32_t st = sbase + (uint32_t)((c + 2) % STAGES) * STAGE_BYTES;
#pragma unroll
            for (int k = 0; k < 8; ++k) {
                cp16(st + dst0 + k * 2048u, a_ptr + (size_t)k * 16 * K);
                cp16(st + STAGE_BYTES_A + dst0 + k * 2048u, b_ptr + (size_t)k * 16 * K);
            }
            a_ptr += BK; b_ptr += BK;
        }
        asm volatile("cp.async.commit_group;" ::: "memory");

        const uint32_t sA = sbase + (uint32_t)(c % STAGES) * STAGE_BYTES;
        const uint32_t sB = sA + STAGE_BYTES_A;

        // kk=0 fragments
#pragma unroll
        for (int mt = 0; mt < 4; ++mt)
            ldsm_x4(af[0][mt], sA + sw128((uint32_t)((a_row + mt * 16) * 128 + a_col16 * 2)));
#pragma unroll
        for (int nt2 = 0; nt2 < 4; ++nt2)
            ldsm_x4(bf[0][nt2], sB + sw128((uint32_t)((b_row + nt2 * 16) * 128 + b_col16 * 2)));

#pragma unroll
        for (int kk = 0; kk < 4; ++kk) {
            const int cur = kk & 1;
            if (kk < 3) {   // prefetch kk+1 fragments before dependent MMAs
                const int nxt = cur ^ 1;
                const int kc = (kk + 1) * 16;
#pragma unroll
                for (int mt = 0; mt < 4; ++mt)
                    ldsm_x4(af[nxt][mt],
                            sA + sw128((uint32_t)((a_row + mt * 16) * 128 + (kc + a_col16) * 2)));
#pragma unroll
                for (int nt2 = 0; nt2 < 4; ++nt2)
                    ldsm_x4(bf[nxt][nt2],
                            sB + sw128((uint32_t)((b_row + nt2 * 16) * 128 + (kc + b_col16) * 2)));
            }
#pragma unroll
            for (int mt = 0; mt < 4; ++mt)
#pragma unroll
                for (int nt2 = 0; nt2 < 4; ++nt2) {
                    mma16816(acc[mt][nt2 * 2 + 0], af[cur][mt], bf[cur][nt2][0], bf[cur][nt2][1]);
                    mma16816(acc[mt][nt2 * 2 + 1], af[cur][mt], bf[cur][nt2][2], bf[cur][nt2][3]);
                }
        }
    }

    // Fused epilogue: x = acc*alpha[col] + bias[col] + resid ; write g_X
    const int er = lane >> 2;           // 0..7
    const int ec = (lane & 3) * 2;      // 0,2,4,6
    const int col0 = n0 + wc * 64;
#pragma unroll
    for (int nt = 0; nt < 8; ++nt) {
        const int col = col0 + nt * 8 + ec;
        const float2 al = *reinterpret_cast<const float2*>(g_alpha + col);
        const float2 bi = *reinterpret_cast<const float2*>(bias + col);
#pragma unroll
        for (int mt = 0; mt < 4; ++mt) {
            const size_t row = (size_t)m0 + wr * 64 + mt * 16 + er;
            const float2 r0v = *reinterpret_cast<const float2*>(resid + row * N + col);
            const float2 r1v = *reinterpret_cast<const float2*>(resid + (row + 8) * N + col);
            float2 v0, v1;
            v0.x = fmaf(acc[mt][nt][0], al.x, bi.x) + r0v.x;
            v0.y = fmaf(acc[mt][nt][1], al.y, bi.y) + r0v.y;
            v1.x = fmaf(acc[mt][nt][2], al.x, bi.x) + r1v.x;
            v1.y = fmaf(acc[mt][nt][3], al.y, bi.y) + r1v.y;
            *reinterpret_cast<float2*>(g_X + row * N + col)       = v0;
            *reinterpret_cast<float2*>(g_X + (row + 8) * N + col) = v1;
        }
    }
}

// ============================================================================
// Kernel 3: LayerNorm — warp per row, two-pass (reload hits L1), low regs
// ============================================================================
__global__ void __launch_bounds__(256) ln_kernel(const float* __restrict__ gamma,
                                                 const float* __restrict__ beta,
                                                 float* __restrict__ out) {
    const size_t row = ((size_t)blockIdx.x * 256 + threadIdx.x) >> 5;
    const int lane = threadIdx.x & 31;
    const float4* xp = reinterpret_cast<const float4*>(g_X + row * N);

    float s1 = 0.f, s2 = 0.f;
#pragma unroll
    for (int j = 0; j < 8; ++j) {
        const float4 v = xp[lane + j * 32];
        s1 += v.x + v.y + v.z + v.w;
        s2 += v.x * v.x + v.y * v.y + v.z * v.z + v.w * v.w;
    }
#pragma unroll
    for (int o = 16; o; o >>= 1) {
        s1 += __shfl_xor_sync(0xffffffffu, s1, o);
        s2 += __shfl_xor_sync(0xffffffffu, s2, o);
    }
    const float mu  = s1 * (1.0f / (float)N);
    const float var = s2 * (1.0f / (float)N) - mu * mu;
    const float rs  = rsqrtf(var + 1e-12f);

    float4* op = reinterpret_cast<float4*>(out + row * N);
    const float4* gp = reinterpret_cast<const float4*>(gamma);
    const float4* bp = reinterpret_cast<const float4*>(beta);
#pragma unroll
    for (int j = 0; j < 8; ++j) {
        const float4 v = xp[lane + j * 32];   // L1 hit (re-read)
        const float4 g = gp[lane + j * 32];
        const float4 b = bp[lane + j * 32];
        float4 o4;
        o4.x = fmaf((v.x - mu) * rs, g.x, b.x);
        o4.y = fmaf((v.y - mu) * rs, g.y, b.y);
        o4.z = fmaf((v.z - mu) * rs, g.z, b.z);
        o4.w = fmaf((v.w - mu) * rs, g.w, b.w);
        op[lane + j * 32] = o4;
    }
}

// ============================================================================
// kernel_launch (graph-capturable: kernel launches only, default stream)
// ============================================================================
extern "C" void kernel_launch(void* const* d_in, const int* in_sizes, int n_in,
                              void* d_out, int out_size) {
    (void)in_sizes; (void)n_in; (void)out_size;
    const float* hidden = (const float*)d_in[0];   // [16,512,4096]
    const float* resid  = (const float*)d_in[1];   // [16,512,1024]
    const float* W      = (const float*)d_in[2];   // [1024,4096]
    const float* bias   = (const float*)d_in[3];   // [1024]
    const float* gamma  = (const float*)d_in[4];   // [1024]
    const float* beta   = (const float*)d_in[5];   // [1024]
    float* out = (float*)d_out;                    // [16,512,1024] fp32

    // fused prep: 1024 W-blocks + 2048 A-blocks (16384 floats per A-block)
    prep_kernel<<<N + (unsigned)(((size_t)M * K) / 16384), 256>>>(W, hidden);

    cudaFuncSetAttribute(gemm_kernel, cudaFuncAttributeMaxDynamicSharedMemorySize, SMEM_GEMM);
    gemm_kernel<<<dim3(N / BN, M / BM), GTHREADS, SMEM_GEMM>>>(resid, bias);

    ln_kernel<<<M / 8, 256>>>(gamma, beta, out);
}